// round 11
// baseline (speedup 1.0000x reference)
#include <cuda_runtime.h>
#include <cuda_fp16.h>
#include <cstdint>

#define MAXN 100000
#define MAXE 1600000
#define IND 128
#define HID 64
#define NB_SCAN 512

// ---------------- scratch ----------------------------------------------------------
__device__ int      d_is64;
__device__ int      d_deg[MAXN];
__device__ float    d_dinv[MAXN];
__device__ __half   d_g[(size_t)MAXN * HID];   // h = x @ W (unscaled, fp16)
__device__ int      d_rowptr[MAXN + 1];
__device__ int      d_cursor[MAXN];
__device__ int      d_srcs[MAXE];
__device__ int      d_bsum[NB_SCAN];
__device__ int      d_boff[NB_SCAN];
__device__ unsigned d_mask[MAXN * 2];          // dropout keep bits, 64/node

// ---------------- threefry-2x32 (JAX partitionable PRNG, key=(0,42)) ---------------
__device__ __forceinline__ void tf_round(unsigned& a, unsigned& b, int r) {
    a += b; b = __funnelshift_l(b, b, r); b ^= a;
}
__device__ __forceinline__ void threefry2x32(unsigned k0, unsigned k1,
                                             unsigned& x0, unsigned& x1) {
    unsigned k2 = k0 ^ k1 ^ 0x1BD11BDAu;
    x0 += k0; x1 += k1;
    tf_round(x0, x1, 13); tf_round(x0, x1, 15); tf_round(x0, x1, 26); tf_round(x0, x1, 6);
    x0 += k1; x1 += k2 + 1u;
    tf_round(x0, x1, 17); tf_round(x0, x1, 29); tf_round(x0, x1, 16); tf_round(x0, x1, 24);
    x0 += k2; x1 += k0 + 2u;
    tf_round(x0, x1, 13); tf_round(x0, x1, 15); tf_round(x0, x1, 26); tf_round(x0, x1, 6);
    x0 += k0; x1 += k1 + 3u;
    tf_round(x0, x1, 17); tf_round(x0, x1, 29); tf_round(x0, x1, 16); tf_round(x0, x1, 24);
    x0 += k1; x1 += k2 + 4u;
    tf_round(x0, x1, 13); tf_round(x0, x1, 15); tf_round(x0, x1, 26); tf_round(x0, x1, 6);
    x0 += k2; x1 += k0 + 5u;
}
__device__ __forceinline__ bool jax_keep(unsigned f) {
    unsigned x0 = 0u, x1 = f;
    threefry2x32(0u, 42u, x0, x1);
    return ((x0 ^ x1) >> 31) == 0u;
}

// ---------------- f32x2 packed math ------------------------------------------------
__device__ __forceinline__ unsigned long long pack2(float x, float y) {
    unsigned long long r;
    asm("mov.b64 %0, {%1, %2};" : "=l"(r) : "f"(x), "f"(y));
    return r;
}
__device__ __forceinline__ void unpack2(unsigned long long v, float& x, float& y) {
    asm("mov.b64 {%0, %1}, %2;" : "=f"(x), "=f"(y) : "l"(v));
}
__device__ __forceinline__ void ffma2(unsigned long long& d, unsigned long long a,
                                      unsigned long long b) {
    asm("fma.rn.f32x2 %0, %1, %2, %0;" : "+l"(d) : "l"(a), "l"(b));
}

// ---------------- kernels ----------------------------------------------------------
// Fused: zero d_deg (all blocks) + dtype detection (block 0 only).
__global__ void k_detect_zero(const unsigned* __restrict__ p, int n) {
    int i = blockIdx.x * blockDim.x + threadIdx.x;
    if (i < n) d_deg[i] = 0;
    if (blockIdx.x == 0) {
        __shared__ int any;
        if (threadIdx.x == 0) any = 0;
        __syncthreads();
        if (threadIdx.x < 128) {
            if (p[1 + 2 * threadIdx.x] != 0u) atomicExch(&any, 1);
        }
        __syncthreads();
        if (threadIdx.x == 0) d_is64 = (any == 0) ? 1 : 0;
    }
}

// In-degree of destinations (scalar form — measured best).
__global__ void k_degree(const int* __restrict__ p, int E) {
    int e = blockIdx.x * blockDim.x + threadIdx.x;
    if (e >= E) return;
    int c;
    if (d_is64) c = (int)((const long long*)p)[E + e];
    else        c = p[E + e];
    atomicAdd(&d_deg[c], 1);
}

// Exclusive scan of d_deg -> d_rowptr (block-local) + fused dinv.
__global__ void k_scanA(int n) {
    __shared__ int s[256];
    int tid = threadIdx.x;
    int i = blockIdx.x * 256 + tid;
    int v = (i < n) ? d_deg[i] : 0;
    if (i < n) d_dinv[i] = rsqrtf((float)(v + 1));
    s[tid] = v;
    __syncthreads();
#pragma unroll
    for (int off = 1; off < 256; off <<= 1) {
        int t = (tid >= off) ? s[tid - off] : 0;
        __syncthreads();
        s[tid] += t;
        __syncthreads();
    }
    if (i < n) d_rowptr[i] = s[tid] - v;
    if (tid == 255) d_bsum[blockIdx.x] = s[255];
}

__global__ void k_scanB(int nb) {
    __shared__ int s[NB_SCAN];
    int tid = threadIdx.x;
    s[tid] = (tid < nb) ? d_bsum[tid] : 0;
    __syncthreads();
#pragma unroll
    for (int off = 1; off < NB_SCAN; off <<= 1) {
        int t = (tid >= off) ? s[tid - off] : 0;
        __syncthreads();
        s[tid] += t;
        __syncthreads();
    }
    d_boff[tid] = (tid == 0) ? 0 : s[tid - 1];
}

__global__ void k_scanC(int n, int E) {
    int i = blockIdx.x * blockDim.x + threadIdx.x;
    if (i < n) {
        int val = d_rowptr[i] + d_boff[i >> 8];
        d_rowptr[i] = val;
        d_cursor[i] = val;
    }
    if (i == 0) d_rowptr[n] = E;
}

// Bucket edges by destination (scalar form — measured best).
__global__ void k_fill(const int* __restrict__ p, int E) {
    int e = blockIdx.x * blockDim.x + threadIdx.x;
    if (e >= E) return;
    int r, c;
    if (d_is64) {
        const long long* q = (const long long*)p;
        r = (int)q[e]; c = (int)q[E + e];
    } else {
        r = p[e]; c = p[E + e];
    }
    int pos = atomicAdd(&d_cursor[c], 1);
    d_srcs[pos] = r;
}

// Dropout keep-bit mask, 32 bits per warp via ballot.  Input-independent.
__global__ void k_mask(int total) {
    int t = blockIdx.x * blockDim.x + threadIdx.x;
    bool kp = (t < total) ? jax_keep((unsigned)t) : false;
    unsigned b = __ballot_sync(0xffffffffu, kp);
    if ((threadIdx.x & 31) == 0 && t < total) d_mask[t >> 5] = b;
}

// h = x @ W via packed f32x2 FMAs; store fp16 (halves gather bytes downstream).
__global__ __launch_bounds__(256) void k_gemm(const float* __restrict__ x,
                                              const float* __restrict__ W,
                                              int n) {
    __shared__ float sW[IND * HID];
    for (int t = threadIdx.x; t < (IND * HID) / 4; t += 256)
        ((float4*)sW)[t] = ((const float4*)W)[t];
    __syncthreads();

    int cg   = threadIdx.x & 7;
    int rl   = threadIdx.x >> 3;
    int row0 = blockIdx.x * 128 + rl * 4;

    const float* px[4];
#pragma unroll
    for (int i = 0; i < 4; i++) {
        int r = row0 + i; if (r >= n) r = n - 1;
        px[i] = x + (size_t)r * IND;
    }

    unsigned long long acc[4][4];
#pragma unroll
    for (int i = 0; i < 4; i++)
#pragma unroll
        for (int j = 0; j < 4; j++) acc[i][j] = 0ull;

    for (int k0 = 0; k0 < IND; k0 += 4) {
        float xr[4][4];
#pragma unroll
        for (int i = 0; i < 4; i++)
            *(float4*)xr[i] = *(const float4*)(px[i] + k0);
#pragma unroll
        for (int kk = 0; kk < 4; kk++) {
            const unsigned long long* wp =
                (const unsigned long long*)(sW + (k0 + kk) * HID + cg * 8);
            unsigned long long w0 = wp[0], w1 = wp[1], w2 = wp[2], w3 = wp[3];
#pragma unroll
            for (int i = 0; i < 4; i++) {
                unsigned long long xx = pack2(xr[i][kk], xr[i][kk]);
                ffma2(acc[i][0], xx, w0);
                ffma2(acc[i][1], xx, w1);
                ffma2(acc[i][2], xx, w2);
                ffma2(acc[i][3], xx, w3);
            }
        }
    }

#pragma unroll
    for (int i = 0; i < 4; i++) {
        int r = row0 + i;
        if (r >= n) break;
        float o[8];
#pragma unroll
        for (int j = 0; j < 4; j++) unpack2(acc[i][j], o[2 * j], o[2 * j + 1]);
        __half2 h0 = __floats2half2_rn(o[0], o[1]);
        __half2 h1 = __floats2half2_rn(o[2], o[3]);
        __half2 h2 = __floats2half2_rn(o[4], o[5]);
        __half2 h3 = __floats2half2_rn(o[6], o[7]);
        uint4 pk;
        pk.x = *(unsigned*)&h0; pk.y = *(unsigned*)&h1;
        pk.z = *(unsigned*)&h2; pk.w = *(unsigned*)&h3;
        *(uint4*)(d_g + (size_t)r * HID + cg * 8) = pk;   // 8 halves = 16 B
    }
}

// Two nodes per warp, fp16 rows, predicated gathers (idle lanes issue NO load),
// unroll-8 for 8 independent 256B gather streams per warp.
__global__ __launch_bounds__(256) void k_aggr(const float* __restrict__ bc,
                                              const float* __restrict__ Wl,
                                              const float* __restrict__ bl,
                                              float* __restrict__ out, int n) {
    int warp = (blockIdx.x * blockDim.x + threadIdx.x) >> 5;
    int lane = threadIdx.x & 31;
    int l16  = lane & 15;
    int hf   = lane >> 4;
    int halfn = (n + 1) >> 1;
    if (warp >= halfn) return;

    int node = hf ? warp + halfn : warp;
    bool valid = node < n;
    if (!valid) node = warp;

    const uint2* g2 = (const uint2*)d_g;     // 4 halves per uint2, 16 uint2 per row
    float dn = d_dinv[node];

    uint2 sraw = g2[(size_t)node * 16 + l16];
    __half2* shp = (__half2*)&sraw;
    float2 s01 = __half22float2(shp[0]);
    float2 s23 = __half22float2(shp[1]);
    float4 acc = make_float4(s01.x * dn, s01.y * dn, s23.x * dn, s23.y * dn);

    int k   = d_rowptr[node];
    int end = d_rowptr[node + 1];

    while (__any_sync(0xffffffffu, k < end)) {
#pragma unroll
        for (int j = 0; j < 8; j++) {
            int idx = k + j;
            bool p = idx < end;
            if (p) {                              // predicated: no load when idle
                int r = d_srcs[idx];
                float dr = d_dinv[r];
                uint2 raw = g2[(size_t)r * 16 + l16];
                __half2* hp = (__half2*)&raw;
                float2 f01 = __half22float2(hp[0]);
                float2 f23 = __half22float2(hp[1]);
                acc.x = fmaf(f01.x, dr, acc.x);
                acc.y = fmaf(f01.y, dr, acc.y);
                acc.z = fmaf(f23.x, dr, acc.z);
                acc.w = fmaf(f23.y, dr, acc.w);
            }
        }
        k += 8;
    }

    // epilogue: bias + relu + precomputed dropout mask + 64->2 projection
    int c0 = 4 * l16;
    float4 bb = ((const float4*)bc)[l16];
    float a0 = fmaxf(fmaf(dn, acc.x, bb.x), 0.f);
    float a1 = fmaxf(fmaf(dn, acc.y, bb.y), 0.f);
    float a2 = fmaxf(fmaf(dn, acc.z, bb.z), 0.f);
    float a3 = fmaxf(fmaf(dn, acc.w, bb.w), 0.f);

    unsigned mw = d_mask[node * 2 + (l16 >> 3)];
    unsigned sh2 = (unsigned)(c0 & 31);
    a0 = ((mw >> sh2) & 1u)       ? a0 * 2.f : 0.f;
    a1 = ((mw >> (sh2 + 1)) & 1u) ? a1 * 2.f : 0.f;
    a2 = ((mw >> (sh2 + 2)) & 1u) ? a2 * 2.f : 0.f;
    a3 = ((mw >> (sh2 + 3)) & 1u) ? a3 * 2.f : 0.f;

    float4 wA = ((const float4*)Wl)[2 * l16];
    float4 wB = ((const float4*)Wl)[2 * l16 + 1];
    float o0 = fmaf(a0, wA.x, fmaf(a1, wA.z, fmaf(a2, wB.x, a3 * wB.z)));
    float o1 = fmaf(a0, wA.y, fmaf(a1, wA.w, fmaf(a2, wB.y, a3 * wB.w)));

#pragma unroll
    for (int off = 8; off > 0; off >>= 1) {
        o0 += __shfl_xor_sync(0xffffffffu, o0, off);
        o1 += __shfl_xor_sync(0xffffffffu, o1, off);
    }
    if (l16 == 0 && valid) {
        out[(size_t)node * 2 + 0] = o0 + bl[0];
        out[(size_t)node * 2 + 1] = o1 + bl[1];
    }
}

// ---------------- launch -----------------------------------------------------------
extern "C" void kernel_launch(void* const* d_in, const int* in_sizes, int n_in,
                              void* d_out, int out_size) {
    const float* x  = (const float*)d_in[0];
    const int*   ei = (const int*)d_in[1];
    const float* Wc = (const float*)d_in[2];
    const float* bc = (const float*)d_in[3];
    const float* Wl = (const float*)d_in[4];
    const float* bl = (const float*)d_in[5];
    float* out = (float*)d_out;

    int n = in_sizes[0] / IND;   // 100000
    int E = in_sizes[1] / 2;     // 1600000
    int nb = (n + 255) / 256;    // 391 (<= NB_SCAN)

    static cudaStream_t s2 = nullptr;
    static cudaEvent_t evFork = nullptr, evJoin = nullptr;
    if (!s2) {
        cudaStreamCreateWithFlags(&s2, cudaStreamNonBlocking);
        cudaEventCreateWithFlags(&evFork, cudaEventDisableTiming);
        cudaEventCreateWithFlags(&evJoin, cudaEventDisableTiming);
    }

    // Fork: GEMM + mask depend only on inputs -> s2, overlapping the edge pipeline.
    cudaEventRecord(evFork, 0);
    cudaStreamWaitEvent(s2, evFork, 0);
    k_gemm<<<(n + 127) / 128, 256, 0, s2>>>(x, Wc, n);
    k_mask<<<(n * 64 + 255) / 256, 256, 0, s2>>>(n * 64);
    cudaEventRecord(evJoin, s2);

    // Edge pipeline on the origin stream.
    k_detect_zero<<<nb, 256>>>((const unsigned*)ei, n);
    k_degree<<<(E + 255) / 256, 256>>>(ei, E);
    k_scanA<<<nb, 256>>>(n);
    k_scanB<<<1, NB_SCAN>>>(nb);
    k_scanC<<<nb, 256>>>(n, E);
    k_fill<<<(E + 255) / 256, 256>>>(ei, E);

    // Join, then fused aggregation + epilogue.
    cudaStreamWaitEvent(0, evJoin, 0);
    int halfn = (n + 1) / 2;
    k_aggr<<<(halfn * 32 + 255) / 256, 256>>>(bc, Wl, bl, out, n);
}

// round 12
// speedup vs baseline: 1.0309x; 1.0309x over previous
#include <cuda_runtime.h>
#include <cuda_fp16.h>
#include <cstdint>

#define MAXN 100000
#define MAXE 1600000
#define IND 128
#define HID 64
#define NB_SCAN 512

// ---------------- scratch ----------------------------------------------------------
__device__ int      d_is64;
__device__ int      d_deg[MAXN];
__device__ float    d_dinv[MAXN];
__device__ __half   d_g[(size_t)MAXN * HID];   // x @ W, then scaled by dinv[row]
__device__ int      d_rowptr[MAXN + 1];
__device__ int      d_pos[MAXE];               // per-edge position within its bucket
__device__ int      d_srcs[MAXE];              // CSR source lists grouped by dst
__device__ int      d_bsum[NB_SCAN];
__device__ int      d_boff[NB_SCAN];
__device__ unsigned d_mask[MAXN * 2];          // dropout keep bits, 64/node

// ---------------- threefry-2x32 (JAX partitionable PRNG, key=(0,42)) ---------------
__device__ __forceinline__ void tf_round(unsigned& a, unsigned& b, int r) {
    a += b; b = __funnelshift_l(b, b, r); b ^= a;
}
__device__ __forceinline__ void threefry2x32(unsigned k0, unsigned k1,
                                             unsigned& x0, unsigned& x1) {
    unsigned k2 = k0 ^ k1 ^ 0x1BD11BDAu;
    x0 += k0; x1 += k1;
    tf_round(x0, x1, 13); tf_round(x0, x1, 15); tf_round(x0, x1, 26); tf_round(x0, x1, 6);
    x0 += k1; x1 += k2 + 1u;
    tf_round(x0, x1, 17); tf_round(x0, x1, 29); tf_round(x0, x1, 16); tf_round(x0, x1, 24);
    x0 += k2; x1 += k0 + 2u;
    tf_round(x0, x1, 13); tf_round(x0, x1, 15); tf_round(x0, x1, 26); tf_round(x0, x1, 6);
    x0 += k0; x1 += k1 + 3u;
    tf_round(x0, x1, 17); tf_round(x0, x1, 29); tf_round(x0, x1, 16); tf_round(x0, x1, 24);
    x0 += k1; x1 += k2 + 4u;
    tf_round(x0, x1, 13); tf_round(x0, x1, 15); tf_round(x0, x1, 26); tf_round(x0, x1, 6);
    x0 += k2; x1 += k0 + 5u;
}
__device__ __forceinline__ bool jax_keep(unsigned f) {
    unsigned x0 = 0u, x1 = f;
    threefry2x32(0u, 42u, x0, x1);
    return ((x0 ^ x1) >> 31) == 0u;
}

// ---------------- f32x2 packed math ------------------------------------------------
__device__ __forceinline__ unsigned long long pack2(float x, float y) {
    unsigned long long r;
    asm("mov.b64 %0, {%1, %2};" : "=l"(r) : "f"(x), "f"(y));
    return r;
}
__device__ __forceinline__ void unpack2(unsigned long long v, float& x, float& y) {
    asm("mov.b64 {%0, %1}, %2;" : "=f"(x), "=f"(y) : "l"(v));
}
__device__ __forceinline__ void ffma2(unsigned long long& d, unsigned long long a,
                                      unsigned long long b) {
    asm("fma.rn.f32x2 %0, %1, %2, %0;" : "+l"(d) : "l"(a), "l"(b));
}

// ---------------- kernels ----------------------------------------------------------
// Fused: zero d_deg (all blocks) + dtype detection (block 0 only).
__global__ void k_detect_zero(const unsigned* __restrict__ p, int n) {
    int i = blockIdx.x * blockDim.x + threadIdx.x;
    if (i < n) d_deg[i] = 0;
    if (blockIdx.x == 0) {
        __shared__ int any;
        if (threadIdx.x == 0) any = 0;
        __syncthreads();
        if (threadIdx.x < 128) {
            if (p[1 + 2 * threadIdx.x] != 0u) atomicExch(&any, 1);
        }
        __syncthreads();
        if (threadIdx.x == 0) d_is64 = (any == 0) ? 1 : 0;
    }
}

// In-degree of destinations; ALSO records each edge's position within its bucket,
// making the later CSR fill atomic-free.
__global__ void k_degree(const int* __restrict__ p, int E) {
    int e = blockIdx.x * blockDim.x + threadIdx.x;
    if (e >= E) return;
    int c;
    if (d_is64) c = (int)((const long long*)p)[E + e];
    else        c = p[E + e];
    d_pos[e] = atomicAdd(&d_deg[c], 1);
}

// Exclusive scan of d_deg -> d_rowptr (block-local) + fused dinv.
__global__ void k_scanA(int n) {
    __shared__ int s[256];
    int tid = threadIdx.x;
    int i = blockIdx.x * 256 + tid;
    int v = (i < n) ? d_deg[i] : 0;
    if (i < n) d_dinv[i] = rsqrtf((float)(v + 1));
    s[tid] = v;
    __syncthreads();
#pragma unroll
    for (int off = 1; off < 256; off <<= 1) {
        int t = (tid >= off) ? s[tid - off] : 0;
        __syncthreads();
        s[tid] += t;
        __syncthreads();
    }
    if (i < n) d_rowptr[i] = s[tid] - v;
    if (tid == 255) d_bsum[blockIdx.x] = s[255];
}

__global__ void k_scanB(int nb) {
    __shared__ int s[NB_SCAN];
    int tid = threadIdx.x;
    s[tid] = (tid < nb) ? d_bsum[tid] : 0;
    __syncthreads();
#pragma unroll
    for (int off = 1; off < NB_SCAN; off <<= 1) {
        int t = (tid >= off) ? s[tid - off] : 0;
        __syncthreads();
        s[tid] += t;
        __syncthreads();
    }
    d_boff[tid] = (tid == 0) ? 0 : s[tid - 1];
}

__global__ void k_scanC(int n, int E) {
    int i = blockIdx.x * blockDim.x + threadIdx.x;
    if (i < n) d_rowptr[i] += d_boff[i >> 8];
    if (i == 0) d_rowptr[n] = E;
}

// Atomic-free CSR fill: position precomputed during degree counting.
__global__ void k_fill(const int* __restrict__ p, int E) {
    int e = blockIdx.x * blockDim.x + threadIdx.x;
    if (e >= E) return;
    int r, c;
    if (d_is64) {
        const long long* q = (const long long*)p;
        r = (int)q[e]; c = (int)q[E + e];
    } else {
        r = p[e]; c = p[E + e];
    }
    d_srcs[d_rowptr[c] + d_pos[e]] = r;
}

// Dropout keep-bit mask, 32 bits per warp via ballot.  Input-independent.
__global__ void k_mask(int total) {
    int t = blockIdx.x * blockDim.x + threadIdx.x;
    bool kp = (t < total) ? jax_keep((unsigned)t) : false;
    unsigned b = __ballot_sync(0xffffffffu, kp);
    if ((threadIdx.x & 31) == 0 && t < total) d_mask[t >> 5] = b;
}

// h = x @ W via packed f32x2 FMAs; store fp16.
__global__ __launch_bounds__(256) void k_gemm(const float* __restrict__ x,
                                              const float* __restrict__ W,
                                              int n) {
    __shared__ float sW[IND * HID];
    for (int t = threadIdx.x; t < (IND * HID) / 4; t += 256)
        ((float4*)sW)[t] = ((const float4*)W)[t];
    __syncthreads();

    int cg   = threadIdx.x & 7;
    int rl   = threadIdx.x >> 3;
    int row0 = blockIdx.x * 128 + rl * 4;

    const float* px[4];
#pragma unroll
    for (int i = 0; i < 4; i++) {
        int r = row0 + i; if (r >= n) r = n - 1;
        px[i] = x + (size_t)r * IND;
    }

    unsigned long long acc[4][4];
#pragma unroll
    for (int i = 0; i < 4; i++)
#pragma unroll
        for (int j = 0; j < 4; j++) acc[i][j] = 0ull;

    for (int k0 = 0; k0 < IND; k0 += 4) {
        float xr[4][4];
#pragma unroll
        for (int i = 0; i < 4; i++)
            *(float4*)xr[i] = *(const float4*)(px[i] + k0);
#pragma unroll
        for (int kk = 0; kk < 4; kk++) {
            const unsigned long long* wp =
                (const unsigned long long*)(sW + (k0 + kk) * HID + cg * 8);
            unsigned long long w0 = wp[0], w1 = wp[1], w2 = wp[2], w3 = wp[3];
#pragma unroll
            for (int i = 0; i < 4; i++) {
                unsigned long long xx = pack2(xr[i][kk], xr[i][kk]);
                ffma2(acc[i][0], xx, w0);
                ffma2(acc[i][1], xx, w1);
                ffma2(acc[i][2], xx, w2);
                ffma2(acc[i][3], xx, w3);
            }
        }
    }

#pragma unroll
    for (int i = 0; i < 4; i++) {
        int r = row0 + i;
        if (r >= n) break;
        float o[8];
#pragma unroll
        for (int j = 0; j < 4; j++) unpack2(acc[i][j], o[2 * j], o[2 * j + 1]);
        __half2 h0 = __floats2half2_rn(o[0], o[1]);
        __half2 h1 = __floats2half2_rn(o[2], o[3]);
        __half2 h2 = __floats2half2_rn(o[4], o[5]);
        __half2 h3 = __floats2half2_rn(o[6], o[7]);
        uint4 pk;
        pk.x = *(unsigned*)&h0; pk.y = *(unsigned*)&h1;
        pk.z = *(unsigned*)&h2; pk.w = *(unsigned*)&h3;
        *(uint4*)(d_g + (size_t)r * HID + cg * 8) = pk;
    }
}

// Scale g rows by dinv[row] in-place (runs on s2 after gemm + scanA; hidden under
// scanB/scanC/fill).  Removes the per-edge dinv gather from k_aggr entirely.
__global__ void k_scale(int n) {
    int t = blockIdx.x * blockDim.x + threadIdx.x;   // one thread per 8 halves
    if (t >= n * 8) return;
    int row = t >> 3;
    float dv = d_dinv[row];
    uint4 pk = *(uint4*)(d_g + (size_t)t * 8);
    __half2* hp = (__half2*)&pk;
#pragma unroll
    for (int j = 0; j < 4; j++) {
        float2 f = __half22float2(hp[j]);
        hp[j] = __floats2half2_rn(f.x * dv, f.y * dv);
    }
    *(uint4*)(d_g + (size_t)t * 8) = pk;
}

// Two nodes per warp, fp16 pre-scaled rows (no dinv gather).  Round-9 winning
// loop form: safe-index loads, predicated accumulate, unroll-4.
__global__ __launch_bounds__(256) void k_aggr(const float* __restrict__ bc,
                                              const float* __restrict__ Wl,
                                              const float* __restrict__ bl,
                                              float* __restrict__ out, int n) {
    int warp = (blockIdx.x * blockDim.x + threadIdx.x) >> 5;
    int lane = threadIdx.x & 31;
    int l16  = lane & 15;
    int hf   = lane >> 4;
    int halfn = (n + 1) >> 1;
    if (warp >= halfn) return;

    int node = hf ? warp + halfn : warp;
    bool valid = node < n;
    if (!valid) node = warp;

    const uint2* g2 = (const uint2*)d_g;
    float dn = d_dinv[node];

    uint2 sraw = g2[(size_t)node * 16 + l16];        // self term (already * dn)
    __half2* shp = (__half2*)&sraw;
    float2 s01 = __half22float2(shp[0]);
    float2 s23 = __half22float2(shp[1]);
    float4 acc = make_float4(s01.x, s01.y, s23.x, s23.y);

    int k   = d_rowptr[node];
    int end = d_rowptr[node + 1];

    while (__any_sync(0xffffffffu, k < end)) {
#pragma unroll
        for (int j = 0; j < 4; j++) {
            int idx = k + j;
            bool p = idx < end;
            int r = p ? d_srcs[idx] : node;          // safe index when idle
            uint2 raw = g2[(size_t)r * 16 + l16];
            if (p) {
                __half2* hp = (__half2*)&raw;
                float2 f01 = __half22float2(hp[0]);
                float2 f23 = __half22float2(hp[1]);
                acc.x += f01.x; acc.y += f01.y;
                acc.z += f23.x; acc.w += f23.y;
            }
        }
        k += 4;
    }

    // epilogue: pre = dn*acc + b; relu; dropout mask; 64->2 projection
    int c0 = 4 * l16;
    float4 bb = ((const float4*)bc)[l16];
    float a0 = fmaxf(fmaf(dn, acc.x, bb.x), 0.f);
    float a1 = fmaxf(fmaf(dn, acc.y, bb.y), 0.f);
    float a2 = fmaxf(fmaf(dn, acc.z, bb.z), 0.f);
    float a3 = fmaxf(fmaf(dn, acc.w, bb.w), 0.f);

    unsigned mw = d_mask[node * 2 + (l16 >> 3)];
    unsigned sh2 = (unsigned)(c0 & 31);
    a0 = ((mw >> sh2) & 1u)       ? a0 * 2.f : 0.f;
    a1 = ((mw >> (sh2 + 1)) & 1u) ? a1 * 2.f : 0.f;
    a2 = ((mw >> (sh2 + 2)) & 1u) ? a2 * 2.f : 0.f;
    a3 = ((mw >> (sh2 + 3)) & 1u) ? a3 * 2.f : 0.f;

    float4 wA = ((const float4*)Wl)[2 * l16];
    float4 wB = ((const float4*)Wl)[2 * l16 + 1];
    float o0 = fmaf(a0, wA.x, fmaf(a1, wA.z, fmaf(a2, wB.x, a3 * wB.z)));
    float o1 = fmaf(a0, wA.y, fmaf(a1, wA.w, fmaf(a2, wB.y, a3 * wB.w)));

#pragma unroll
    for (int off = 8; off > 0; off >>= 1) {
        o0 += __shfl_xor_sync(0xffffffffu, o0, off);
        o1 += __shfl_xor_sync(0xffffffffu, o1, off);
    }
    if (l16 == 0 && valid) {
        out[(size_t)node * 2 + 0] = o0 + bl[0];
        out[(size_t)node * 2 + 1] = o1 + bl[1];
    }
}

// ---------------- launch -----------------------------------------------------------
extern "C" void kernel_launch(void* const* d_in, const int* in_sizes, int n_in,
                              void* d_out, int out_size) {
    const float* x  = (const float*)d_in[0];
    const int*   ei = (const int*)d_in[1];
    const float* Wc = (const float*)d_in[2];
    const float* bc = (const float*)d_in[3];
    const float* Wl = (const float*)d_in[4];
    const float* bl = (const float*)d_in[5];
    float* out = (float*)d_out;

    int n = in_sizes[0] / IND;   // 100000
    int E = in_sizes[1] / 2;     // 1600000
    int nb = (n + 255) / 256;    // 391 (<= NB_SCAN)

    static cudaStream_t s2 = nullptr;
    static cudaEvent_t evFork = nullptr, evScanA = nullptr, evJoin = nullptr;
    if (!s2) {
        cudaStreamCreateWithFlags(&s2, cudaStreamNonBlocking);
        cudaEventCreateWithFlags(&evFork, cudaEventDisableTiming);
        cudaEventCreateWithFlags(&evScanA, cudaEventDisableTiming);
        cudaEventCreateWithFlags(&evJoin, cudaEventDisableTiming);
    }

    // Fork: GEMM + mask depend only on inputs -> s2, overlapping the edge pipeline.
    cudaEventRecord(evFork, 0);
    cudaStreamWaitEvent(s2, evFork, 0);
    k_gemm<<<(n + 127) / 128, 256, 0, s2>>>(x, Wc, n);
    k_mask<<<(n * 64 + 255) / 256, 256, 0, s2>>>(n * 64);

    // Edge pipeline on the origin stream.
    k_detect_zero<<<nb, 256>>>((const unsigned*)ei, n);
    k_degree<<<(E + 255) / 256, 256>>>(ei, E);
    k_scanA<<<nb, 256>>>(n);
    cudaEventRecord(evScanA, 0);

    // s2: scale g by dinv (needs gemm [same stream] + scanA [event]).
    cudaStreamWaitEvent(s2, evScanA, 0);
    k_scale<<<(n * 8 + 255) / 256, 256, 0, s2>>>(n);
    cudaEventRecord(evJoin, s2);

    // Origin continues: finish scan + atomic-free fill.
    k_scanB<<<1, NB_SCAN>>>(nb);
    k_scanC<<<nb, 256>>>(n, E);
    k_fill<<<(E + 255) / 256, 256>>>(ei, E);

    // Join, then fused aggregation + epilogue.
    cudaStreamWaitEvent(0, evJoin, 0);
    int halfn = (n + 1) / 2;
    k_aggr<<<(halfn * 32 + 255) / 256, 256>>>(bc, Wl, bl, out, n);
}

// round 13
// speedup vs baseline: 1.0411x; 1.0098x over previous
#include <cuda_runtime.h>
#include <cuda_fp16.h>
#include <cstdint>

#define MAXN 100000
#define MAXE 1600000
#define IND 128
#define HID 64
#define NB_SCAN 512

// ---------------- scratch ----------------------------------------------------------
__device__ int      d_deg[MAXN];               // zeroed by k_aggr epilogue (invariant)
__device__ float    d_dinv[MAXN];
__device__ __half   d_g[(size_t)MAXN * HID];   // x @ W, then scaled by dinv[row]
__device__ int      d_rowptr[MAXN + 1];
__device__ int      d_pos[MAXE];               // per-edge position within its bucket
__device__ int      d_srcs[MAXE];              // CSR source lists grouped by dst
__device__ int      d_bsum[NB_SCAN];
__device__ unsigned d_mask[MAXN * 2];          // dropout keep bits, 64/node

// ---------------- threefry-2x32 (JAX partitionable PRNG, key=(0,42)) ---------------
__device__ __forceinline__ void tf_round(unsigned& a, unsigned& b, int r) {
    a += b; b = __funnelshift_l(b, b, r); b ^= a;
}
__device__ __forceinline__ void threefry2x32(unsigned k0, unsigned k1,
                                             unsigned& x0, unsigned& x1) {
    unsigned k2 = k0 ^ k1 ^ 0x1BD11BDAu;
    x0 += k0; x1 += k1;
    tf_round(x0, x1, 13); tf_round(x0, x1, 15); tf_round(x0, x1, 26); tf_round(x0, x1, 6);
    x0 += k1; x1 += k2 + 1u;
    tf_round(x0, x1, 17); tf_round(x0, x1, 29); tf_round(x0, x1, 16); tf_round(x0, x1, 24);
    x0 += k2; x1 += k0 + 2u;
    tf_round(x0, x1, 13); tf_round(x0, x1, 15); tf_round(x0, x1, 26); tf_round(x0, x1, 6);
    x0 += k0; x1 += k1 + 3u;
    tf_round(x0, x1, 17); tf_round(x0, x1, 29); tf_round(x0, x1, 16); tf_round(x0, x1, 24);
    x0 += k1; x1 += k2 + 4u;
    tf_round(x0, x1, 13); tf_round(x0, x1, 15); tf_round(x0, x1, 26); tf_round(x0, x1, 6);
    x0 += k2; x1 += k0 + 5u;
}
__device__ __forceinline__ bool jax_keep(unsigned f) {
    unsigned x0 = 0u, x1 = f;
    threefry2x32(0u, 42u, x0, x1);
    return ((x0 ^ x1) >> 31) == 0u;
}

// ---------------- f32x2 packed math ------------------------------------------------
__device__ __forceinline__ unsigned long long pack2(float x, float y) {
    unsigned long long r;
    asm("mov.b64 %0, {%1, %2};" : "=l"(r) : "f"(x), "f"(y));
    return r;
}
__device__ __forceinline__ void unpack2(unsigned long long v, float& x, float& y) {
    asm("mov.b64 {%0, %1}, %2;" : "=f"(x), "=f"(y) : "l"(v));
}
__device__ __forceinline__ void ffma2(unsigned long long& d, unsigned long long a,
                                      unsigned long long b) {
    asm("fma.rn.f32x2 %0, %1, %2, %0;" : "+l"(d) : "l"(a), "l"(b));
}

// Block-local int64/int32 detection: odd 32-bit words of the first 128 edge slots
// are ALL zero iff the buffer is little-endian int64 (ids < 2^31).
__device__ __forceinline__ bool block_is64(const unsigned* p) {
    __shared__ int s_any;
    if (threadIdx.x == 0) s_any = 0;
    __syncthreads();
    if (threadIdx.x < 128 && p[1 + 2 * threadIdx.x] != 0u) s_any = 1;
    __syncthreads();
    return s_any == 0;
}

// ---------------- kernels ----------------------------------------------------------
// In-degree of destinations; records each edge's bucket position (atomic-free fill).
// d_deg arrives zeroed (module init on call 1; k_aggr epilogue afterwards).
__global__ void k_degree(const int* __restrict__ p, int E) {
    bool is64 = block_is64((const unsigned*)p);
    int e = blockIdx.x * blockDim.x + threadIdx.x;
    if (e >= E) return;
    int c = is64 ? (int)((const long long*)p)[E + e] : p[E + e];
    d_pos[e] = atomicAdd(&d_deg[c], 1);
}

// Exclusive scan of d_deg -> d_rowptr (block-local) + fused dinv.
__global__ void k_scanA(int n) {
    __shared__ int s[256];
    int tid = threadIdx.x;
    int i = blockIdx.x * 256 + tid;
    int v = (i < n) ? d_deg[i] : 0;
    if (i < n) d_dinv[i] = rsqrtf((float)(v + 1));
    s[tid] = v;
    __syncthreads();
#pragma unroll
    for (int off = 1; off < 256; off <<= 1) {
        int t = (tid >= off) ? s[tid - off] : 0;
        __syncthreads();
        s[tid] += t;
        __syncthreads();
    }
    if (i < n) d_rowptr[i] = s[tid] - v;
    if (tid == 255) d_bsum[blockIdx.x] = s[255];
}

// Finish scan: each block reduces bsum[0..b) itself (<=391 adds), no middle kernel.
__global__ void k_scanC(int n, int E, int nb) {
    __shared__ int wsum[8];
    int b = blockIdx.x;
    int tid = threadIdx.x;
    int lane = tid & 31, wid = tid >> 5;

    int acc = 0;
    for (int j = tid; j < b; j += 256) acc += d_bsum[j];
#pragma unroll
    for (int off = 16; off > 0; off >>= 1)
        acc += __shfl_xor_sync(0xffffffffu, acc, off);
    if (lane == 0) wsum[wid] = acc;
    __syncthreads();
    int boff = wsum[0] + wsum[1] + wsum[2] + wsum[3]
             + wsum[4] + wsum[5] + wsum[6] + wsum[7];

    int i = b * 256 + tid;
    if (i < n) d_rowptr[i] += boff;
    if (i == 0) d_rowptr[n] = E;
}

// Atomic-free CSR fill (position precomputed during degree counting).
__global__ void k_fill(const int* __restrict__ p, int E) {
    bool is64 = block_is64((const unsigned*)p);
    int e = blockIdx.x * blockDim.x + threadIdx.x;
    if (e >= E) return;
    int r, c;
    if (is64) {
        const long long* q = (const long long*)p;
        r = (int)q[e]; c = (int)q[E + e];
    } else {
        r = p[e]; c = p[E + e];
    }
    d_srcs[d_rowptr[c] + d_pos[e]] = r;
}

// Dropout keep-bit mask, 32 bits per warp via ballot.  Input-independent.
__global__ void k_mask(int total) {
    int t = blockIdx.x * blockDim.x + threadIdx.x;
    bool kp = (t < total) ? jax_keep((unsigned)t) : false;
    unsigned b = __ballot_sync(0xffffffffu, kp);
    if ((threadIdx.x & 31) == 0 && t < total) d_mask[t >> 5] = b;
}

// h = x @ W via packed f32x2 FMAs; store fp16.
__global__ __launch_bounds__(256) void k_gemm(const float* __restrict__ x,
                                              const float* __restrict__ W,
                                              int n) {
    __shared__ float sW[IND * HID];
    for (int t = threadIdx.x; t < (IND * HID) / 4; t += 256)
        ((float4*)sW)[t] = ((const float4*)W)[t];
    __syncthreads();

    int cg   = threadIdx.x & 7;
    int rl   = threadIdx.x >> 3;
    int row0 = blockIdx.x * 128 + rl * 4;

    const float* px[4];
#pragma unroll
    for (int i = 0; i < 4; i++) {
        int r = row0 + i; if (r >= n) r = n - 1;
        px[i] = x + (size_t)r * IND;
    }

    unsigned long long acc[4][4];
#pragma unroll
    for (int i = 0; i < 4; i++)
#pragma unroll
        for (int j = 0; j < 4; j++) acc[i][j] = 0ull;

    for (int k0 = 0; k0 < IND; k0 += 4) {
        float xr[4][4];
#pragma unroll
        for (int i = 0; i < 4; i++)
            *(float4*)xr[i] = *(const float4*)(px[i] + k0);
#pragma unroll
        for (int kk = 0; kk < 4; kk++) {
            const unsigned long long* wp =
                (const unsigned long long*)(sW + (k0 + kk) * HID + cg * 8);
            unsigned long long w0 = wp[0], w1 = wp[1], w2 = wp[2], w3 = wp[3];
#pragma unroll
            for (int i = 0; i < 4; i++) {
                unsigned long long xx = pack2(xr[i][kk], xr[i][kk]);
                ffma2(acc[i][0], xx, w0);
                ffma2(acc[i][1], xx, w1);
                ffma2(acc[i][2], xx, w2);
                ffma2(acc[i][3], xx, w3);
            }
        }
    }

#pragma unroll
    for (int i = 0; i < 4; i++) {
        int r = row0 + i;
        if (r >= n) break;
        float o[8];
#pragma unroll
        for (int j = 0; j < 4; j++) unpack2(acc[i][j], o[2 * j], o[2 * j + 1]);
        __half2 h0 = __floats2half2_rn(o[0], o[1]);
        __half2 h1 = __floats2half2_rn(o[2], o[3]);
        __half2 h2 = __floats2half2_rn(o[4], o[5]);
        __half2 h3 = __floats2half2_rn(o[6], o[7]);
        uint4 pk;
        pk.x = *(unsigned*)&h0; pk.y = *(unsigned*)&h1;
        pk.z = *(unsigned*)&h2; pk.w = *(unsigned*)&h3;
        *(uint4*)(d_g + (size_t)r * HID + cg * 8) = pk;
    }
}

// Scale g rows by dinv[row] in-place (s2, hidden under scanC/fill).
__global__ void k_scale(int n) {
    int t = blockIdx.x * blockDim.x + threadIdx.x;   // one thread per 8 halves
    if (t >= n * 8) return;
    int row = t >> 3;
    float dv = d_dinv[row];
    uint4 pk = *(uint4*)(d_g + (size_t)t * 8);
    __half2* hp = (__half2*)&pk;
#pragma unroll
    for (int j = 0; j < 4; j++) {
        float2 f = __half22float2(hp[j]);
        hp[j] = __floats2half2_rn(f.x * dv, f.y * dv);
    }
    *(uint4*)(d_g + (size_t)t * 8) = pk;
}

// Two nodes per warp, fp16 pre-scaled rows.  Uniform trip count (no per-iter vote),
// round-9 winning body form.  Epilogue also zeroes d_deg (next-call invariant).
__global__ __launch_bounds__(256) void k_aggr(const float* __restrict__ bc,
                                              const float* __restrict__ Wl,
                                              const float* __restrict__ bl,
                                              float* __restrict__ out, int n) {
    int warp = (blockIdx.x * blockDim.x + threadIdx.x) >> 5;
    int lane = threadIdx.x & 31;
    int l16  = lane & 15;
    int hf   = lane >> 4;
    int halfn = (n + 1) >> 1;
    if (warp >= halfn) return;

    int node = hf ? warp + halfn : warp;
    bool valid = node < n;
    if (!valid) node = warp;

    const uint2* g2 = (const uint2*)d_g;
    float dn = d_dinv[node];

    uint2 sraw = g2[(size_t)node * 16 + l16];        // self term (already * dn)
    __half2* shp = (__half2*)&sraw;
    float2 s01 = __half22float2(shp[0]);
    float2 s23 = __half22float2(shp[1]);
    float4 acc = make_float4(s01.x, s01.y, s23.x, s23.y);

    int k   = d_rowptr[node];
    int end = d_rowptr[node + 1];
    int m   = __reduce_max_sync(0xffffffffu, (end - k + 3) >> 2);

    for (int i = 0; i < m; i++) {
#pragma unroll
        for (int j = 0; j < 4; j++) {
            int idx = k + j;
            bool pl = idx < end;
            int r = pl ? d_srcs[idx] : node;         // safe index when idle
            uint2 raw = g2[(size_t)r * 16 + l16];
            if (pl) {
                __half2* hp = (__half2*)&raw;
                float2 f01 = __half22float2(hp[0]);
                float2 f23 = __half22float2(hp[1]);
                acc.x += f01.x; acc.y += f01.y;
                acc.z += f23.x; acc.w += f23.y;
            }
        }
        k += 4;
    }

    // epilogue: pre = dn*acc + b; relu; dropout mask; 64->2 projection
    int c0 = 4 * l16;
    float4 bb = ((const float4*)bc)[l16];
    float a0 = fmaxf(fmaf(dn, acc.x, bb.x), 0.f);
    float a1 = fmaxf(fmaf(dn, acc.y, bb.y), 0.f);
    float a2 = fmaxf(fmaf(dn, acc.z, bb.z), 0.f);
    float a3 = fmaxf(fmaf(dn, acc.w, bb.w), 0.f);

    unsigned mw = d_mask[node * 2 + (l16 >> 3)];
    unsigned sh2 = (unsigned)(c0 & 31);
    a0 = ((mw >> sh2) & 1u)       ? a0 * 2.f : 0.f;
    a1 = ((mw >> (sh2 + 1)) & 1u) ? a1 * 2.f : 0.f;
    a2 = ((mw >> (sh2 + 2)) & 1u) ? a2 * 2.f : 0.f;
    a3 = ((mw >> (sh2 + 3)) & 1u) ? a3 * 2.f : 0.f;

    float4 wA = ((const float4*)Wl)[2 * l16];
    float4 wB = ((const float4*)Wl)[2 * l16 + 1];
    float o0 = fmaf(a0, wA.x, fmaf(a1, wA.z, fmaf(a2, wB.x, a3 * wB.z)));
    float o1 = fmaf(a0, wA.y, fmaf(a1, wA.w, fmaf(a2, wB.y, a3 * wB.w)));

#pragma unroll
    for (int off = 8; off > 0; off >>= 1) {
        o0 += __shfl_xor_sync(0xffffffffu, o0, off);
        o1 += __shfl_xor_sync(0xffffffffu, o1, off);
    }
    if (l16 == 0 && valid) {
        out[(size_t)node * 2 + 0] = o0 + bl[0];
        out[(size_t)node * 2 + 1] = o1 + bl[1];
        d_deg[node] = 0;                 // maintain zero-invariant for next call
    }
}

// ---------------- launch -----------------------------------------------------------
extern "C" void kernel_launch(void* const* d_in, const int* in_sizes, int n_in,
                              void* d_out, int out_size) {
    const float* x  = (const float*)d_in[0];
    const int*   ei = (const int*)d_in[1];
    const float* Wc = (const float*)d_in[2];
    const float* bc = (const float*)d_in[3];
    const float* Wl = (const float*)d_in[4];
    const float* bl = (const float*)d_in[5];
    float* out = (float*)d_out;

    int n = in_sizes[0] / IND;   // 100000
    int E = in_sizes[1] / 2;     // 1600000
    int nb = (n + 255) / 256;    // 391 (<= NB_SCAN)

    static cudaStream_t s2 = nullptr, s3 = nullptr;
    static cudaEvent_t evFork = nullptr, evScanA = nullptr,
                       evJoin = nullptr, evMask = nullptr;
    if (!s2) {
        cudaStreamCreateWithFlags(&s2, cudaStreamNonBlocking);
        cudaStreamCreateWithFlags(&s3, cudaStreamNonBlocking);
        cudaEventCreateWithFlags(&evFork, cudaEventDisableTiming);
        cudaEventCreateWithFlags(&evScanA, cudaEventDisableTiming);
        cudaEventCreateWithFlags(&evJoin, cudaEventDisableTiming);
        cudaEventCreateWithFlags(&evMask, cudaEventDisableTiming);
    }

    // Fork: gemm (s2) and mask (s3) depend only on inputs; run concurrently.
    cudaEventRecord(evFork, 0);
    cudaStreamWaitEvent(s2, evFork, 0);
    cudaStreamWaitEvent(s3, evFork, 0);
    k_gemm<<<(n + 127) / 128, 256, 0, s2>>>(x, Wc, n);
    k_mask<<<(n * 64 + 255) / 256, 256, 0, s3>>>(n * 64);
    cudaEventRecord(evMask, s3);

    // Edge pipeline on the origin stream (d_deg pre-zeroed by invariant).
    k_degree<<<(E + 255) / 256, 256>>>(ei, E);
    k_scanA<<<nb, 256>>>(n);
    cudaEventRecord(evScanA, 0);

    // s2: scale g by dinv (needs gemm [stream order] + scanA [event]).
    cudaStreamWaitEvent(s2, evScanA, 0);
    k_scale<<<(n * 8 + 255) / 256, 256, 0, s2>>>(n);
    cudaEventRecord(evJoin, s2);

    // Origin: finish scan + atomic-free fill.
    k_scanC<<<nb, 256>>>(n, E, nb);
    k_fill<<<(E + 255) / 256, 256>>>(ei, E);

    // Join all, then fused aggregation + epilogue.
    cudaStreamWaitEvent(0, evJoin, 0);
    cudaStreamWaitEvent(0, evMask, 0);
    int halfn = (n + 1) / 2;
    k_aggr<<<(halfn * 32 + 255) / 256, 256>>>(bc, Wl, bl, out, n);
}